// round 16
// baseline (speedup 1.0000x reference)
#include <cuda_runtime.h>
#include <cuda_fp16.h>
#include <cstdint>
#include <math.h>

#define N_ATOMS  10000
#define N_STRUCT 100
#define NPSEUDO  4
#define NSPECIES 4
#define NFEAT    4096
#define HIDDEN   256
#define NPACK    2112            // 4 * 528 triangular packing
#define KT0      (NPACK / 32)    // 66 k-tiles of 32
#define KT1      (HIDDEN / 32)   // 8
#define MBLK64   157             // ceil(10000/64)
#define APAD     (MBLK64 * 64)   // 10048

// ---------------- scratch (static device globals; no allocation) ----------------
__device__ uint32_t g_featP[(size_t)MBLK64 * KT0 * 1024];             // 42.4 MB
__device__ uint32_t g_W0f[(size_t)NPSEUDO * KT0 * 4096];              // 4.3 MB
__device__ uint32_t g_W1f[(size_t)NPSEUDO * KT1 * 4096];              // 0.5 MB
__device__ uint32_t g_h1f[(size_t)NPSEUDO * MBLK64 * KT1 * 1024];     // 20.6 MB
__device__ uchar2   g_qr[528];                                        // tri LUT

__device__ __forceinline__ float silu(float x) { return x / (1.0f + expf(-x)); }

__device__ __forceinline__ uint32_t smem_u32(const void* p) {
    uint32_t a;
    asm("{ .reg .u64 t; cvta.to.shared.u64 t, %1; cvt.u32.u64 %0, t; }" : "=r"(a) : "l"(p));
    return a;
}

// triangular decode: t2 in [0,528) -> (q, r), q<=r<32
__device__ __forceinline__ void tri_decode(int t2, int& q, int& r) {
    q = (int)((65.0f - sqrtf(4225.0f - 8.0f * (float)t2)) * 0.5f);
    if (q < 0) q = 0;
    while (q * (65 - q) / 2 > t2) q--;
    while ((q + 1) * (64 - q) / 2 <= t2) q++;
    r = q + (t2 - q * (65 - q) / 2);
}

// B-fragment halfword offset for element (k within 32-tile, col c within 256)
__device__ __forceinline__ size_t b_frag_off(int kt, int kin, int c, int ktiles, int p) {
    int kmma = kin >> 4, k16 = kin & 15;
    int khalf = k16 >> 3, kpos = k16 & 7;
    int tig = kpos >> 1, hw = kpos & 1;
    int nt = c >> 3, grp = c & 7, lane = grp * 4 + tig;
    size_t idx = (size_t)(p * ktiles + kt);
    idx = idx * 32 + nt;
    idx = idx * 2 + kmma;
    idx = idx * 32 + lane;
    idx = idx * 2 + khalf;
    return idx * 2 + hw;
}

// ---------------- merged: LUT build + output zero + W1 fragment-permute ----------------
// grid (HIDDEN, NPSEUDO), block 256
__global__ void init_w1_kernel(const float* __restrict__ W1, float* __restrict__ out) {
    const int c = threadIdx.x;
    const int k = blockIdx.x;                // 0..255
    const int p = blockIdx.y;

    if (p == 0) {
        int idx = k * 256 + c;
        if (idx < 528) {
            int q, r;
            tri_decode(idx, q, r);
            g_qr[idx] = make_uchar2((unsigned char)q, (unsigned char)r);
        }
        if (idx < N_STRUCT) out[idx] = 0.0f;
    }

    float v = W1[((size_t)p * HIDDEN + k) * HIDDEN + c];
    ((__half*)g_W1f)[b_frag_off(k >> 5, k & 31, c, KT1, p)] = __float2half_rn(v);
}

// ---------------- W0: symmetrize + fp16 fragment-permute, k-pair -> STG.32 ----------------
__global__ void convert_w0_kernel(const float* __restrict__ W0) {
    const int c  = threadIdx.x;              // hidden col
    const int k2 = blockIdx.x * 2;           // even packed k
    const int p  = blockIdx.y;
    const int l  = (k2 >= 1584) ? 3 : ((k2 >= 1056) ? 2 : ((k2 >= 528) ? 1 : 0));
    const int t2 = k2 - l * 528;
    uchar2 qr0 = g_qr[t2];
    uchar2 qr1 = g_qr[t2 + 1];
    const size_t base = (size_t)p * NFEAT * HIDDEN + (size_t)l * 1024 * HIDDEN;

    float v0 = W0[base + (size_t)(qr0.x * 32 + qr0.y) * HIDDEN + c];
    if (qr0.x != qr0.y) v0 += W0[base + (size_t)(qr0.y * 32 + qr0.x) * HIDDEN + c];
    float v1 = W0[base + (size_t)(qr1.x * 32 + qr1.y) * HIDDEN + c];
    if (qr1.x != qr1.y) v1 += W0[base + (size_t)(qr1.y * 32 + qr1.x) * HIDDEN + c];

    const int kt = k2 >> 5, kin = k2 & 31;
    const int kmma = kin >> 4, k16 = kin & 15;
    const int khalf = k16 >> 3, tig = (k16 & 7) >> 1;
    const int nt = c >> 3, grp = c & 7, lane = grp * 4 + tig;
    size_t idx = (size_t)(p * KT0 + kt);
    idx = idx * 32 + nt;
    idx = idx * 2 + kmma;
    idx = idx * 32 + lane;
    idx = idx * 2 + khalf;
    __half2 h = __floats2half2_rn(v0, v1);
    g_W0f[idx] = *(uint32_t*)&h;
}

// ---------------- power spectrum -> fp16 fragment-major features ----------------
__global__ void features_kernel(const float* __restrict__ c0,
                                const float* __restrict__ c1,
                                const float* __restrict__ c2,
                                const float* __restrict__ c3) {
    __shared__ float4 scT[512];
    __shared__ uchar2 lut[528];
    const int a0 = blockIdx.x * 4;
    const int t = threadIdx.x;

    #pragma unroll
    for (int j = 0; j < 3; j++) {
        int idx = t + 256 * j;
        if (idx < 528) lut[idx] = g_qr[idx];
    }
    #pragma unroll
    for (int j = 0; j < 2; j++) {
        int idx = t + 256 * j;
        float4 v;
        float* vp = (float*)&v;
        #pragma unroll
        for (int i = 0; i < 4; i++) {
            int a = a0 + i;
            float x = 0.0f;
            if (a < N_ATOMS) {
                if (idx < 32)        x = c0[(size_t)a * 32  + idx];
                else if (idx < 128)  x = c1[(size_t)a * 96  + (idx - 32)];
                else if (idx < 288)  x = c2[(size_t)a * 160 + (idx - 128)];
                else                 x = c3[(size_t)a * 224 + (idx - 288)];
            }
            vp[i] = x;
        }
        scT[idx] = v;
    }
    __syncthreads();

    const int b64 = a0 >> 6;
    const int b16 = (a0 & 63) >> 4;
    const size_t aoffb = (size_t)b64 * (KT0 * 1024) + b16 * 256;
    int aoff_i[4];
    #pragma unroll
    for (int i = 0; i < 4; i++) {
        int r16 = (a0 & 15) + i;
        aoff_i[i] = (r16 & 7) * 16 + (r16 >> 3);
    }

    const float cg[4]   = {1.0f, 0.57735026919f, 0.44721359550f, 0.37796447301f};
    const int   loffs[4] = {0, 32, 128, 288};

    const size_t kbase0 = (size_t)(t >> 4) * 1024 + ((t >> 3) & 1) * 128
                        + (t & 3) * 4 + ((t >> 2) & 1) * 2;
    uint32_t* dst = g_featP;

    #pragma unroll
    for (int j = 0; j < 5; j++) {
        int k2 = 2 * t + 512 * j;
        if (k2 < NPACK) {
            int l = (k2 >= 1584) ? 3 : ((k2 >= 1056) ? 2 : ((k2 >= 528) ? 1 : 0));
            int t2 = k2 - l * 528;
            uchar2 qr0 = lut[t2];
            uchar2 qr1 = lut[t2 + 1];
            int lo = loffs[l];
            int qo0 = lo + qr0.x, ro0 = lo + qr0.y;
            int qo1 = lo + qr1.x, ro1 = lo + qr1.y;
            float s0[4] = {0.f, 0.f, 0.f, 0.f};
            float s1[4] = {0.f, 0.f, 0.f, 0.f};
            int nm = 2 * l + 1;
            for (int m = 0; m < nm; m++) {
                float4 A0 = scT[m * 32 + qo0];
                float4 B0 = scT[m * 32 + ro0];
                float4 A1 = scT[m * 32 + qo1];
                float4 B1 = scT[m * 32 + ro1];
                const float* a0p = (const float*)&A0;
                const float* b0p = (const float*)&B0;
                const float* a1p = (const float*)&A1;
                const float* b1p = (const float*)&B1;
                #pragma unroll
                for (int i = 0; i < 4; i++) {
                    s0[i] += a0p[i] * b0p[i];
                    s1[i] += a1p[i] * b1p[i];
                }
            }
            float cgl = cg[l];
            size_t kb = aoffb + kbase0 + (size_t)j * 16384;
            #pragma unroll
            for (int i = 0; i < 4; i++) {
                __half2 h = __floats2half2_rn(cgl * s0[i], cgl * s1[i]);
                dst[kb + aoff_i[i]] = *(uint32_t*)&h;
            }
        }
    }
}

// ---------------- fp16 mma (fp32 accumulate) ----------------
__device__ __forceinline__ void mma_f16(float c[4], const uint32_t a[4], const uint32_t b[2]) {
    asm volatile(
        "mma.sync.aligned.m16n8k16.row.col.f32.f16.f16.f32 "
        "{%0,%1,%2,%3}, {%4,%5,%6,%7}, {%8,%9}, {%0,%1,%2,%3};\n"
        : "+f"(c[0]), "+f"(c[1]), "+f"(c[2]), "+f"(c[3])
        : "r"(a[0]), "r"(a[1]), "r"(a[2]), "r"(a[3]), "r"(b[0]), "r"(b[1]));
}

// ================= unified fp16 GEMM: 64x128 tile, CTA=128 threads, 4 CTAs/SM =================
// MODE 0: A=featP, B=W0f -> g_h1f (fragment-major fp16), epi silu(pw*x). KT=66.
// MODE 1: A=g_h1f, B=W1f -> fused energy, smem-staged segmented reduction. KT=8.
#define G_STFL   3072                        // u32 per stage: A 1024 + B 2048 (12KB)
#define G_STAGES 4
#define G_DSMEM  (G_STAGES * G_STFL * 4)     // 48KB

template<int KT, int MODE>
__global__ void __launch_bounds__(128, 4)
gemm_f16_kernel(const float* __restrict__ combW, const int* __restrict__ species,
                const float* __restrict__ W2, const int* __restrict__ sid,
                float* __restrict__ out) {
    extern __shared__ uint32_t smu[];
    __shared__ float eacc[64];

    const int p   = blockIdx.x >> 1;
    const int nh  = blockIdx.x & 1;
    const int b64 = blockIdx.y;
    const int m0  = b64 * 64;

    const uint32_t* Ag = (MODE == 0)
        ? g_featP + (size_t)b64 * KT0 * 1024
        : g_h1f   + (size_t)(p * MBLK64 + b64) * (KT1 * 1024);
    const uint32_t* Bg = ((MODE == 0) ? g_W0f + (size_t)p * KT0 * 4096
                                      : g_W1f + (size_t)p * KT1 * 4096) + nh * 2048;

    const int tid  = threadIdx.x;
    const int warp = tid >> 5;
    const int lane = tid & 31;
    const int grp  = lane >> 2;
    const int tig  = lane & 3;
    const int wmB  = (warp & 1) * 2;     // m16-block base (2 per warp)
    const int wnB  = (warp >> 1) * 8;    // n8-block base within 16 (8 per warp)

    if (MODE == 1 && tid < 64) eacc[tid] = 0.0f;

    float acc[2][8][4];
    #pragma unroll
    for (int mt = 0; mt < 2; mt++)
        #pragma unroll
        for (int nt = 0; nt < 8; nt++)
            #pragma unroll
            for (int i = 0; i < 4; i++) acc[mt][nt][i] = 0.0f;

    const uint32_t sbase = smem_u32(smu);

    // 12KB linear copy per k-tile: 768 x 16B, 6 per thread (L1-bypass: no intra-SM reuse)
    auto load_tile = [&](int kt, int b) {
        const uint4* srcA = (const uint4*)(Ag + (size_t)kt * 1024);
        const uint4* srcB = (const uint4*)(Bg + (size_t)kt * 4096);
        const uint32_t dst0 = sbase + (uint32_t)b * (G_STFL * 4);
        #pragma unroll
        for (int j = 0; j < 6; j++) {
            int c = tid + 128 * j;
            const uint4* src = (c < 256) ? (srcA + c) : (srcB + (c - 256));
            uint32_t dst = dst0 + (uint32_t)c * 16u;
            asm volatile("cp.async.cg.shared.global [%0], [%1], 16;\n"
                         :: "r"(dst), "l"(src));
        }
        asm volatile("cp.async.commit_group;\n");
    };

    load_tile(0, 0);
    load_tile(1, 1);
    load_tile(2, 2);

    for (int kt = 0; kt < KT; kt++) {
        const int b = kt & (G_STAGES - 1);
        if (kt + 2 < KT)      asm volatile("cp.async.wait_group 2;\n");
        else if (kt + 1 < KT) asm volatile("cp.async.wait_group 1;\n");
        else                  asm volatile("cp.async.wait_group 0;\n");
        __syncthreads();
        if (kt + 3 < KT) load_tile(kt + 3, (kt + 3) & (G_STAGES - 1));

        const uint32_t* As = smu + (size_t)b * G_STFL;
        const uint32_t* Bs = As + 1024;

        #pragma unroll
        for (int km = 0; km < 2; km++) {
            uint4 a0 = *(const uint4*)(As + ((wmB    ) * 2 + km) * 128 + lane * 4);
            uint4 a1 = *(const uint4*)(As + ((wmB + 1) * 2 + km) * 128 + lane * 4);
            uint2 bv[8];
            #pragma unroll
            for (int nt = 0; nt < 8; nt++)
                bv[nt] = *(const uint2*)(Bs + ((wnB + nt) * 2 + km) * 64 + lane * 2);
            const uint32_t* af0 = (const uint32_t*)&a0;
            const uint32_t* af1 = (const uint32_t*)&a1;
            #pragma unroll
            for (int nt = 0; nt < 8; nt++) {
                const uint32_t* bf = (const uint32_t*)&bv[nt];
                mma_f16(acc[0][nt], af0, bf);
                mma_f16(acc[1][nt], af1, bf);
            }
        }
        __syncthreads();
    }

    // ---------------- epilogue ----------------
    #pragma unroll
    for (int mt = 0; mt < 2; mt++) {
        const int b16 = wmB + mt;
        const int r0 = m0 + b16 * 16 + grp;
        const int r1 = r0 + 8;
        if (MODE == 0) {
            float pw0 = (r0 < N_ATOMS) ? combW[p * NSPECIES + species[r0]] : 0.0f;
            float pw1 = (r1 < N_ATOMS) ? combW[p * NSPECIES + species[r1]] : 0.0f;
            #pragma unroll
            for (int nt = 0; nt < 8; nt++) {
                const int c = (nh * 16 + wnB + nt) * 8 + tig * 2;   // global hidden col
                float x0 = silu(acc[mt][nt][0] * pw0);
                float x1 = silu(acc[mt][nt][1] * pw0);
                float x2 = silu(acc[mt][nt][2] * pw1);
                float x3 = silu(acc[mt][nt][3] * pw1);
                __half2 v01 = __floats2half2_rn(x0, x1);
                __half2 v23 = __floats2half2_rn(x2, x3);
                const int kt1 = c >> 5, kmma = (c >> 4) & 1, khalf = (c >> 3) & 1;
                size_t idx = (size_t)(p * MBLK64 + b64) * (KT1 * 1024);
                size_t sub = (size_t)(kt1 * 4 + b16);
                sub = sub * 2 + kmma;
                sub = sub * 32 + lane;
                uint32_t* base = g_h1f + idx + sub * 4;
                base[2 * khalf    ] = *(uint32_t*)&v01;
                base[2 * khalf + 1] = *(uint32_t*)&v23;
            }
        } else {
            const float* W2p = W2 + p * HIDDEN;
            float sum0 = 0.0f, sum1 = 0.0f;
            #pragma unroll
            for (int nt = 0; nt < 8; nt++) {
                const int c = (nh * 16 + wnB + nt) * 8 + tig * 2;
                float w0 = W2p[c], w1 = W2p[c + 1];
                sum0 += silu(acc[mt][nt][0]) * w0 + silu(acc[mt][nt][1]) * w1;
                sum1 += silu(acc[mt][nt][2]) * w0 + silu(acc[mt][nt][3]) * w1;
            }
            sum0 += __shfl_xor_sync(0xffffffffu, sum0, 1);
            sum0 += __shfl_xor_sync(0xffffffffu, sum0, 2);
            sum1 += __shfl_xor_sync(0xffffffffu, sum1, 1);
            sum1 += __shfl_xor_sync(0xffffffffu, sum1, 2);
            if (tig == 0) {
                atomicAdd(&eacc[b16 * 16 + grp    ], sum0);
                atomicAdd(&eacc[b16 * 16 + grp + 8], sum1);
            }
        }
    }

    if (MODE == 1) {
        __syncthreads();
        if (tid < 64) {
            // warp-level segmented suffix-sum over sorted sids; heads do the atomics
            int row = m0 + tid;
            float v = eacc[tid];
            int s = (row < N_ATOMS) ? sid[row] : 0x7fffffff;
            #pragma unroll
            for (int d = 1; d < 32; d <<= 1) {
                float vn = __shfl_down_sync(0xffffffffu, v, d);
                int   sn = __shfl_down_sync(0xffffffffu, s, d);
                if (lane + d < 32 && sn == s) v += vn;
            }
            int sp = __shfl_up_sync(0xffffffffu, s, 1);
            bool head = (lane == 0) || (sp != s);
            if (head && s != 0x7fffffff) atomicAdd(&out[s], v);
        }
    }
}

// ---------------- launch ----------------
extern "C" void kernel_launch(void* const* d_in, const int* in_sizes, int n_in,
                              void* d_out, int out_size) {
    const float* c0      = (const float*)d_in[0];
    const float* c1      = (const float*)d_in[1];
    const float* c2      = (const float*)d_in[2];
    const float* c3      = (const float*)d_in[3];
    const int*   species = (const int*)d_in[4];
    const int*   sid     = (const int*)d_in[5];
    const float* combW   = (const float*)d_in[6];
    const float* W0      = (const float*)d_in[7];
    const float* W1      = (const float*)d_in[8];
    const float* W2      = (const float*)d_in[9];
    float* out = (float*)d_out;

    static bool attr_set = false;
    if (!attr_set) {
        cudaFuncSetAttribute(gemm_f16_kernel<KT0, 0>,
                             cudaFuncAttributeMaxDynamicSharedMemorySize, G_DSMEM);
        cudaFuncSetAttribute(gemm_f16_kernel<KT1, 1>,
                             cudaFuncAttributeMaxDynamicSharedMemorySize, G_DSMEM);
        attr_set = true;
    }

    {
        dim3 g(HIDDEN, NPSEUDO);             // builds LUT + zeroes out + converts W1
        init_w1_kernel<<<g, 256>>>(W1, out);
    }
    {
        dim3 g(NPACK / 2, NPSEUDO);          // k-pair per block, STG.32 writes
        convert_w0_kernel<<<g, 256>>>(W0);
    }

    features_kernel<<<APAD / 4, 256>>>(c0, c1, c2, c3);

    {
        dim3 g(NPSEUDO * 2, MBLK64);
        gemm_f16_kernel<KT0, 0><<<g, 128, G_DSMEM>>>(combW, species, W2, sid, out);
        gemm_f16_kernel<KT1, 1><<<g, 128, G_DSMEM>>>(combW, species, W2, sid, out);
    }
}

// round 17
// speedup vs baseline: 1.0280x; 1.0280x over previous
#include <cuda_runtime.h>
#include <cuda_fp16.h>
#include <cstdint>
#include <math.h>

#define N_ATOMS  10000
#define N_STRUCT 100
#define NPSEUDO  4
#define NSPECIES 4
#define NFEAT    4096
#define HIDDEN   256
#define NPACK    2112            // 4 * 528 triangular packing
#define KT0      (NPACK / 32)    // 66 k-tiles of 32
#define KT1      (HIDDEN / 32)   // 8
#define MBLK64   157             // ceil(10000/64)
#define APAD     (MBLK64 * 64)   // 10048

// block-range partition of the mega-prep kernel
#define PREP_FEAT_BLOCKS (APAD / 4)                    // 2512
#define PREP_W0_BLOCKS   ((NPACK / 2) * NPSEUDO)       // 4224
#define PREP_W1_BLOCKS   (HIDDEN * NPSEUDO / 1)        // p*256+k -> 1024 blocks
#define PREP_TOTAL (PREP_FEAT_BLOCKS + PREP_W0_BLOCKS + 1024)

// ---------------- scratch (static device globals; no allocation) ----------------
__device__ uint32_t g_featP[(size_t)MBLK64 * KT0 * 1024];             // 42.4 MB
__device__ uint32_t g_W0f[(size_t)NPSEUDO * KT0 * 4096];              // 4.3 MB
__device__ uint32_t g_W1f[(size_t)NPSEUDO * KT1 * 4096];              // 0.5 MB
__device__ uint32_t g_h1f[(size_t)NPSEUDO * MBLK64 * KT1 * 1024];     // 20.6 MB

__device__ __forceinline__ float silu(float x) { return x / (1.0f + expf(-x)); }

__device__ __forceinline__ uint32_t smem_u32(const void* p) {
    uint32_t a;
    asm("{ .reg .u64 t; cvta.to.shared.u64 t, %1; cvt.u32.u64 %0, t; }" : "=r"(a) : "l"(p));
    return a;
}

// triangular decode: t2 in [0,528) -> (q, r), q<=r<32
__device__ __forceinline__ void tri_decode(int t2, int& q, int& r) {
    q = (int)((65.0f - sqrtf(4225.0f - 8.0f * (float)t2)) * 0.5f);
    if (q < 0) q = 0;
    while (q * (65 - q) / 2 > t2) q--;
    while ((q + 1) * (64 - q) / 2 <= t2) q++;
    r = q + (t2 - q * (65 - q) / 2);
}

// B-fragment halfword offset, km-interleaved layout:
// u32(kt,kin,c) = base(kt)*4096 + nt*128 + lane*4 + kmma*2 + khalf ; hw = kin&1
__device__ __forceinline__ size_t b_frag_off(int kt, int kin, int c, int ktiles, int p) {
    int kmma = kin >> 4, k16 = kin & 15;
    int khalf = k16 >> 3, kpos = k16 & 7;
    int tig = kpos >> 1, hw = kpos & 1;
    int nt = c >> 3, grp = c & 7, lane = grp * 4 + tig;
    size_t idx = (size_t)(p * ktiles + kt) * 4096
               + (size_t)(nt * 128 + lane * 4 + kmma * 2 + khalf);
    return idx * 2 + hw;
}

// ================= MEGA-PREP: features ∪ convert_w0 ∪ convert_w1 ∪ zero-out =================
__global__ void __launch_bounds__(256)
prep_kernel(const float* __restrict__ c0, const float* __restrict__ c1,
            const float* __restrict__ c2, const float* __restrict__ c3,
            const float* __restrict__ W0, const float* __restrict__ W1,
            float* __restrict__ out) {
    const int bx = blockIdx.x;
    const int t = threadIdx.x;

    if (bx < PREP_FEAT_BLOCKS) {
        // -------- features: 4 atoms/block, fragment-major fp16 output --------
        __shared__ float4 scT[512];
        __shared__ uchar2 lut[528];
        const int a0 = bx * 4;

        #pragma unroll
        for (int j = 0; j < 3; j++) {
            int idx = t + 256 * j;
            if (idx < 528) {
                int q, r;
                tri_decode(idx, q, r);
                lut[idx] = make_uchar2((unsigned char)q, (unsigned char)r);
            }
        }
        #pragma unroll
        for (int j = 0; j < 2; j++) {
            int idx = t + 256 * j;
            float4 v;
            float* vp = (float*)&v;
            #pragma unroll
            for (int i = 0; i < 4; i++) {
                int a = a0 + i;
                float x = 0.0f;
                if (a < N_ATOMS) {
                    if (idx < 32)        x = c0[(size_t)a * 32  + idx];
                    else if (idx < 128)  x = c1[(size_t)a * 96  + (idx - 32)];
                    else if (idx < 288)  x = c2[(size_t)a * 160 + (idx - 128)];
                    else                 x = c3[(size_t)a * 224 + (idx - 288)];
                }
                vp[i] = x;
            }
            scT[idx] = v;
        }
        __syncthreads();

        const int b64 = a0 >> 6;
        const int b16 = (a0 & 63) >> 4;
        const size_t aoffb = (size_t)b64 * (KT0 * 1024) + b16 * 256;
        int aoff_i[4];
        #pragma unroll
        for (int i = 0; i < 4; i++) {
            int r16 = (a0 & 15) + i;
            aoff_i[i] = (r16 & 7) * 16 + (r16 >> 3);
        }

        const float cg[4]   = {1.0f, 0.57735026919f, 0.44721359550f, 0.37796447301f};
        const int   loffs[4] = {0, 32, 128, 288};
        const size_t kbase0 = (size_t)(t >> 4) * 1024 + ((t >> 3) & 1) * 128
                            + (t & 3) * 4 + ((t >> 2) & 1) * 2;
        uint32_t* dst = g_featP;

        #pragma unroll
        for (int j = 0; j < 5; j++) {
            int k2 = 2 * t + 512 * j;
            if (k2 < NPACK) {
                int l = (k2 >= 1584) ? 3 : ((k2 >= 1056) ? 2 : ((k2 >= 528) ? 1 : 0));
                int t2 = k2 - l * 528;
                uchar2 qr0 = lut[t2];
                uchar2 qr1 = lut[t2 + 1];
                int lo = loffs[l];
                int qo0 = lo + qr0.x, ro0 = lo + qr0.y;
                int qo1 = lo + qr1.x, ro1 = lo + qr1.y;
                float s0[4] = {0.f, 0.f, 0.f, 0.f};
                float s1[4] = {0.f, 0.f, 0.f, 0.f};
                int nm = 2 * l + 1;
                for (int m = 0; m < nm; m++) {
                    float4 A0 = scT[m * 32 + qo0];
                    float4 B0 = scT[m * 32 + ro0];
                    float4 A1 = scT[m * 32 + qo1];
                    float4 B1 = scT[m * 32 + ro1];
                    const float* a0p = (const float*)&A0;
                    const float* b0p = (const float*)&B0;
                    const float* a1p = (const float*)&A1;
                    const float* b1p = (const float*)&B1;
                    #pragma unroll
                    for (int i = 0; i < 4; i++) {
                        s0[i] += a0p[i] * b0p[i];
                        s1[i] += a1p[i] * b1p[i];
                    }
                }
                float cgl = cg[l];
                size_t kb = aoffb + kbase0 + (size_t)j * 16384;
                #pragma unroll
                for (int i = 0; i < 4; i++) {
                    __half2 h = __floats2half2_rn(cgl * s0[i], cgl * s1[i]);
                    dst[kb + aoff_i[i]] = *(uint32_t*)&h;
                }
            }
        }
    } else if (bx < PREP_FEAT_BLOCKS + PREP_W0_BLOCKS) {
        // -------- convert_w0: symmetrize + fp16 fragment-permute, k-pair -> STG.32 --------
        const int bw = bx - PREP_FEAT_BLOCKS;
        const int c  = t;
        const int k2 = (bw % (NPACK / 2)) * 2;
        const int p  = bw / (NPACK / 2);
        const int l  = (k2 >= 1584) ? 3 : ((k2 >= 1056) ? 2 : ((k2 >= 528) ? 1 : 0));
        const int t2 = k2 - l * 528;
        int q0, r0, q1, r1;
        tri_decode(t2, q0, r0);
        tri_decode(t2 + 1, q1, r1);
        const size_t base = (size_t)p * NFEAT * HIDDEN + (size_t)l * 1024 * HIDDEN;

        float v0 = W0[base + (size_t)(q0 * 32 + r0) * HIDDEN + c];
        if (q0 != r0) v0 += W0[base + (size_t)(r0 * 32 + q0) * HIDDEN + c];
        float v1 = W0[base + (size_t)(q1 * 32 + r1) * HIDDEN + c];
        if (q1 != r1) v1 += W0[base + (size_t)(r1 * 32 + q1) * HIDDEN + c];

        const int kt = k2 >> 5, kin = k2 & 31;
        const int kmma = kin >> 4, k16 = kin & 15;
        const int khalf = k16 >> 3, tig = (k16 & 7) >> 1;
        const int nt = c >> 3, grp = c & 7, lane = grp * 4 + tig;
        size_t idx = (size_t)(p * KT0 + kt) * 4096
                   + (size_t)(nt * 128 + lane * 4 + kmma * 2 + khalf);
        __half2 h = __floats2half2_rn(v0, v1);
        g_W0f[idx] = *(uint32_t*)&h;
    } else {
        // -------- convert_w1 + zero-out --------
        const int bw = bx - PREP_FEAT_BLOCKS - PREP_W0_BLOCKS;   // 0..1023
        const int p = bw >> 8;
        const int k = bw & 255;
        const int c = t;
        if (p == 0 && k == 0 && c < N_STRUCT) out[c] = 0.0f;
        float v = W1[((size_t)p * HIDDEN + k) * HIDDEN + c];
        ((__half*)g_W1f)[b_frag_off(k >> 5, k & 31, c, KT1, p)] = __float2half_rn(v);
    }
}

// ---------------- fp16 mma (fp32 accumulate) ----------------
__device__ __forceinline__ void mma_f16(float c[4], const uint32_t a[4], const uint32_t b[2]) {
    asm volatile(
        "mma.sync.aligned.m16n8k16.row.col.f32.f16.f16.f32 "
        "{%0,%1,%2,%3}, {%4,%5,%6,%7}, {%8,%9}, {%0,%1,%2,%3};\n"
        : "+f"(c[0]), "+f"(c[1]), "+f"(c[2]), "+f"(c[3])
        : "r"(a[0]), "r"(a[1]), "r"(a[2]), "r"(a[3]), "r"(b[0]), "r"(b[1]));
}

// ================= unified fp16 GEMM: 64x128 tile, CTA=128 threads, 4 CTAs/SM =================
// B layout km-interleaved: one LDS.128 per nt covers both kmma.
// MODE 0: A=featP, B=W0f -> g_h1f (fragment-major fp16), epi silu(pw*x). KT=66.
// MODE 1: A=g_h1f, B=W1f -> fused energy, smem-staged segmented reduction. KT=8.
#define G_STFL   3072                        // u32 per stage: A 1024 + B 2048 (12KB)
#define G_STAGES 4
#define G_DSMEM  (G_STAGES * G_STFL * 4)     // 48KB

template<int KT, int MODE>
__global__ void __launch_bounds__(128, 4)
gemm_f16_kernel(const float* __restrict__ combW, const int* __restrict__ species,
                const float* __restrict__ W2, const int* __restrict__ sid,
                float* __restrict__ out) {
    extern __shared__ uint32_t smu[];
    __shared__ float eacc[64];

    const int p   = blockIdx.x >> 1;
    const int nh  = blockIdx.x & 1;
    const int b64 = blockIdx.y;
    const int m0  = b64 * 64;

    const uint32_t* Ag = (MODE == 0)
        ? g_featP + (size_t)b64 * KT0 * 1024
        : g_h1f   + (size_t)(p * MBLK64 + b64) * (KT1 * 1024);
    const uint32_t* Bg = ((MODE == 0) ? g_W0f + (size_t)p * KT0 * 4096
                                      : g_W1f + (size_t)p * KT1 * 4096) + nh * 2048;

    const int tid  = threadIdx.x;
    const int warp = tid >> 5;
    const int lane = tid & 31;
    const int grp  = lane >> 2;
    const int tig  = lane & 3;
    const int wmB  = (warp & 1) * 2;     // m16-block base (2 per warp)
    const int wnB  = (warp >> 1) * 8;    // n8-block base within 16 (8 per warp)

    if (MODE == 1 && tid < 64) eacc[tid] = 0.0f;

    float acc[2][8][4];
    #pragma unroll
    for (int mt = 0; mt < 2; mt++)
        #pragma unroll
        for (int nt = 0; nt < 8; nt++)
            #pragma unroll
            for (int i = 0; i < 4; i++) acc[mt][nt][i] = 0.0f;

    const uint32_t sbase = smem_u32(smu);

    // 12KB linear copy per k-tile: 768 x 16B, 6 per thread (L1-bypass)
    auto load_tile = [&](int kt, int b) {
        const uint4* srcA = (const uint4*)(Ag + (size_t)kt * 1024);
        const uint4* srcB = (const uint4*)(Bg + (size_t)kt * 4096);
        const uint32_t dst0 = sbase + (uint32_t)b * (G_STFL * 4);
        #pragma unroll
        for (int j = 0; j < 6; j++) {
            int c = tid + 128 * j;
            const uint4* src = (c < 256) ? (srcA + c) : (srcB + (c - 256));
            uint32_t dst = dst0 + (uint32_t)c * 16u;
            asm volatile("cp.async.cg.shared.global [%0], [%1], 16;\n"
                         :: "r"(dst), "l"(src));
        }
        asm volatile("cp.async.commit_group;\n");
    };

    load_tile(0, 0);
    load_tile(1, 1);
    load_tile(2, 2);

    for (int kt = 0; kt < KT; kt++) {
        const int b = kt & (G_STAGES - 1);
        if (kt + 2 < KT)      asm volatile("cp.async.wait_group 2;\n");
        else if (kt + 1 < KT) asm volatile("cp.async.wait_group 1;\n");
        else                  asm volatile("cp.async.wait_group 0;\n");
        __syncthreads();
        if (kt + 3 < KT) load_tile(kt + 3, (kt + 3) & (G_STAGES - 1));

        const uint4* As4 = (const uint4*)(smu + (size_t)b * G_STFL);          // A: [b16][km][lane]
        const uint4* Bs4 = (const uint4*)(smu + (size_t)b * G_STFL + 1024);   // B: [nt][lane] (km-interleaved)

        uint4 a00 = As4[((wmB    ) * 2 + 0) * 32 + lane];
        uint4 a01 = As4[((wmB    ) * 2 + 1) * 32 + lane];
        uint4 a10 = As4[((wmB + 1) * 2 + 0) * 32 + lane];
        uint4 a11 = As4[((wmB + 1) * 2 + 1) * 32 + lane];

        #pragma unroll
        for (int nt = 0; nt < 8; nt++) {
            uint4 b4 = Bs4[(wnB + nt) * 32 + lane];
            const uint32_t* b4p = (const uint32_t*)&b4;
            mma_f16(acc[0][nt], (const uint32_t*)&a00, b4p);       // km 0
            mma_f16(acc[1][nt], (const uint32_t*)&a10, b4p);
            mma_f16(acc[0][nt], (const uint32_t*)&a01, b4p + 2);   // km 1
            mma_f16(acc[1][nt], (const uint32_t*)&a11, b4p + 2);
        }
        __syncthreads();
    }

    // ---------------- epilogue ----------------
    #pragma unroll
    for (int mt = 0; mt < 2; mt++) {
        const int b16 = wmB + mt;
        const int r0 = m0 + b16 * 16 + grp;
        const int r1 = r0 + 8;
        if (MODE == 0) {
            float pw0 = (r0 < N_ATOMS) ? combW[p * NSPECIES + species[r0]] : 0.0f;
            float pw1 = (r1 < N_ATOMS) ? combW[p * NSPECIES + species[r1]] : 0.0f;
            #pragma unroll
            for (int nt = 0; nt < 8; nt++) {
                const int c = (nh * 16 + wnB + nt) * 8 + tig * 2;   // global hidden col
                float x0 = silu(acc[mt][nt][0] * pw0);
                float x1 = silu(acc[mt][nt][1] * pw0);
                float x2 = silu(acc[mt][nt][2] * pw1);
                float x3 = silu(acc[mt][nt][3] * pw1);
                __half2 v01 = __floats2half2_rn(x0, x1);
                __half2 v23 = __floats2half2_rn(x2, x3);
                const int kt1 = c >> 5, kmma = (c >> 4) & 1, khalf = (c >> 3) & 1;
                size_t idx = (size_t)(p * MBLK64 + b64) * (KT1 * 1024);
                size_t sub = (size_t)(kt1 * 4 + b16);
                sub = sub * 2 + kmma;
                sub = sub * 32 + lane;
                uint32_t* base = g_h1f + idx + sub * 4;
                base[2 * khalf    ] = *(uint32_t*)&v01;
                base[2 * khalf + 1] = *(uint32_t*)&v23;
            }
        } else {
            const float* W2p = W2 + p * HIDDEN;
            float sum0 = 0.0f, sum1 = 0.0f;
            #pragma unroll
            for (int nt = 0; nt < 8; nt++) {
                const int c = (nh * 16 + wnB + nt) * 8 + tig * 2;
                float w0 = W2p[c], w1 = W2p[c + 1];
                sum0 += silu(acc[mt][nt][0]) * w0 + silu(acc[mt][nt][1]) * w1;
                sum1 += silu(acc[mt][nt][2]) * w0 + silu(acc[mt][nt][3]) * w1;
            }
            sum0 += __shfl_xor_sync(0xffffffffu, sum0, 1);
            sum0 += __shfl_xor_sync(0xffffffffu, sum0, 2);
            sum1 += __shfl_xor_sync(0xffffffffu, sum1, 1);
            sum1 += __shfl_xor_sync(0xffffffffu, sum1, 2);
            if (tig == 0) {
                atomicAdd(&eacc[b16 * 16 + grp    ], sum0);
                atomicAdd(&eacc[b16 * 16 + grp + 8], sum1);
            }
        }
    }

    if (MODE == 1) {
        __syncthreads();
        if (tid < 64) {
            // warp-level segmented suffix-sum over sorted sids; heads do the atomics
            int row = m0 + tid;
            float v = eacc[tid];
            int s = (row < N_ATOMS) ? sid[row] : 0x7fffffff;
            #pragma unroll
            for (int d = 1; d < 32; d <<= 1) {
                float vn = __shfl_down_sync(0xffffffffu, v, d);
                int   sn = __shfl_down_sync(0xffffffffu, s, d);
                if (lane + d < 32 && sn == s) v += vn;
            }
            int sp = __shfl_up_sync(0xffffffffu, s, 1);
            bool head = (lane == 0) || (sp != s);
            if (head && s != 0x7fffffff) atomicAdd(&out[s], v);
        }
    }
}

// ---------------- launch ----------------
extern "C" void kernel_launch(void* const* d_in, const int* in_sizes, int n_in,
                              void* d_out, int out_size) {
    const float* c0      = (const float*)d_in[0];
    const float* c1      = (const float*)d_in[1];
    const float* c2      = (const float*)d_in[2];
    const float* c3      = (const float*)d_in[3];
    const int*   species = (const int*)d_in[4];
    const int*   sid     = (const int*)d_in[5];
    const float* combW   = (const float*)d_in[6];
    const float* W0      = (const float*)d_in[7];
    const float* W1      = (const float*)d_in[8];
    const float* W2      = (const float*)d_in[9];
    float* out = (float*)d_out;

    static bool attr_set = false;
    if (!attr_set) {
        cudaFuncSetAttribute(gemm_f16_kernel<KT0, 0>,
                             cudaFuncAttributeMaxDynamicSharedMemorySize, G_DSMEM);
        cudaFuncSetAttribute(gemm_f16_kernel<KT1, 1>,
                             cudaFuncAttributeMaxDynamicSharedMemorySize, G_DSMEM);
        attr_set = true;
    }

    // one mega-prep launch: features + W0 symmetrize/permute + W1 permute + zero-out
    prep_kernel<<<PREP_TOTAL, 256>>>(c0, c1, c2, c3, W0, W1, out);

    {
        dim3 g(NPSEUDO * 2, MBLK64);
        gemm_f16_kernel<KT0, 0><<<g, 128, G_DSMEM>>>(combW, species, W2, sid, out);
        gemm_f16_kernel<KT1, 1><<<g, 128, G_DSMEM>>>(combW, species, W2, sid, out);
    }
}